// round 10
// baseline (speedup 1.0000x reference)
#include <cuda_runtime.h>

#define WL_L      2048
#define WL_LMASK  2047
#define WL_D      32
#define WL_B      16
#define WL_NT     256                 // 8 warps, one per d-plane

#define WL_G      8                   // d-planes per CTA
#define WL_T      128                 // outputs per plane per CTA
#define WL_HALO   112                 // x halo (28 quads), >= 105 back-reach
#define WL_EXT    (WL_T + WL_HALO)    // 240 floats = 60 quads
#define WL_NCHUNK (WL_L / WL_T)       // 16
#define WL_NDG    (WL_D / WL_G)       // 4

__global__ __launch_bounds__(WL_NT) void wavelet_db4_kernel(
    const float* __restrict__ x,       // (B, L, D)
    const float* __restrict__ w_dec,   // (4, L, L) — only 8 taps read
    const float* __restrict__ v_dec,   // (4, L, L) — only 8 taps read
    float* __restrict__ out)           // (B, D, L, 5)
{
    __shared__ __align__(16) float xs [WL_G][WL_EXT];
    __shared__ __align__(16) float v1s[WL_G][WL_EXT];
    __shared__ float gs[8];
    __shared__ float hs[8];
    __shared__ float2 cs[22];          // (cg2[t], ch2[t]) composite taps

    const int tid   = threadIdx.x;
    const int blk   = blockIdx.x;
    const int chunk = blk & (WL_NCHUNK - 1);
    const int dg    = (blk >> 4) & (WL_NDG - 1);
    const int b     = blk >> 6;
    const int M0    = chunk * WL_T;
    const int base  = M0 - WL_HALO;

    const int p    = tid >> 5;        // plane 0..7 == warp id
    const int lane = tid & 31;
    const int hq   = lane - 4;        // halo quad id; valid hq in [7,27] (lanes 11..31)

    // ── warp 0: base taps + composite taps (other warps proceed to gather)
    if (p == 0) {
        if (lane < 8) {
            int col = (WL_L - lane) & WL_LMASK;   // f[0][0][(0-i) mod L] = tap[i]
            gs[lane] = v_dec[col];
            hs[lane] = w_dec[col];
        }
        __syncwarp();
        if (lane < 22) {
            // cg2[t] = sum_k g[k]*g[t-2k];  ch2[t] = sum_k h[k]*g[t-2k]
            float cg = 0.f, ch = 0.f;
            #pragma unroll
            for (int k = 0; k < 8; k++) {
                int i = lane - 2 * k;
                if (i >= 0 && i < 8) {
                    cg += gs[k] * gs[i];
                    ch += hs[k] * gs[i];
                }
            }
            cs[lane] = make_float2(cg, ch);
        }
    }

    // ── gather: 8 adjacent d per x-row (two LDG.128 per row), all threads
    {
        const float* xp = x + ((size_t)b * WL_L * WL_D) + dg * WL_G;
        for (int l = tid; l < WL_EXT; l += WL_NT) {
            int gl = (base + l) & WL_LMASK;
            const float4* rp = (const float4*)(xp + (size_t)gl * WL_D);
            float4 q0 = rp[0], q1 = rp[1];
            xs[0][l] = q0.x; xs[1][l] = q0.y; xs[2][l] = q0.z; xs[3][l] = q0.w;
            xs[4][l] = q1.x; xs[5][l] = q1.y; xs[6][l] = q1.z; xs[7][l] = q1.w;
        }
    }
    __syncthreads();   // the ONLY CTA-wide barrier

    float h[8];
    #pragma unroll
    for (int i = 0; i < 8; i++) h[i] = hs[i];

    const float4* xs4 = (const float4*)(&xs [p][0]);
    const float4* v1r = (const float4*)(&v1s[p][0]);
    float4*       v1w = (float4*)(&v1s[p][0]);

    const int b4 = 28 + lane;         // this thread's output quad (28..59)

    float w0[4], w1[4];

    // ── stage A: x → v1 (cg2), w1 (ch2), w0 (h); split window to cap live regs
    {
        float v1a[4] = {0.f, 0.f, 0.f, 0.f};
        #pragma unroll
        for (int j = 0; j < 4; j++) { w1[j] = 0.f; w0[j] = 0.f; }

        // phase 1: quads b4-6..b4-2 (win idx 0..19), taps t=9..21 (idx 3..18)
        {
            float winA[20];
            #pragma unroll
            for (int kk = 0; kk < 5; kk++) {
                float4 qv = xs4[b4 - 6 + kk];
                winA[4*kk+0] = qv.x; winA[4*kk+1] = qv.y;
                winA[4*kk+2] = qv.z; winA[4*kk+3] = qv.w;
            }
            #pragma unroll
            for (int t = 9; t < 22; t++) {
                float2 c = cs[t];
                #pragma unroll
                for (int j = 0; j < 4; j++) {
                    v1a[j] += c.x * winA[24 + j - t];
                    w1[j]  += c.y * winA[24 + j - t];
                }
            }
        }
        // phase 2: quads b4-2..b4 (idx 16..27 → winB[0..11]), taps t=0..8 + h
        {
            float winB[12];
            #pragma unroll
            for (int kk = 0; kk < 3; kk++) {
                float4 qv = xs4[b4 - 2 + kk];
                winB[4*kk+0] = qv.x; winB[4*kk+1] = qv.y;
                winB[4*kk+2] = qv.z; winB[4*kk+3] = qv.w;
            }
            #pragma unroll
            for (int t = 0; t < 9; t++) {
                float2 c = cs[t];
                #pragma unroll
                for (int j = 0; j < 4; j++) {
                    v1a[j] += c.x * winB[8 + j - t];
                    w1[j]  += c.y * winB[8 + j - t];
                }
            }
            #pragma unroll
            for (int i = 0; i < 8; i++) {
                #pragma unroll
                for (int j = 0; j < 4; j++)
                    w0[j] += h[i] * winB[8 + j - i];
            }
        }
        v1w[b4] = make_float4(v1a[0], v1a[1], v1a[2], v1a[3]);
    }

    // halo v1 (quads 7..27), cg2 only, same split-window shape
    if (hq >= 7) {
        float a[4] = {0.f, 0.f, 0.f, 0.f};
        {
            float winA[20];
            #pragma unroll
            for (int kk = 0; kk < 5; kk++) {
                float4 qv = xs4[hq - 6 + kk];
                winA[4*kk+0] = qv.x; winA[4*kk+1] = qv.y;
                winA[4*kk+2] = qv.z; winA[4*kk+3] = qv.w;
            }
            #pragma unroll
            for (int t = 9; t < 22; t++) {
                float cg = cs[t].x;
                #pragma unroll
                for (int j = 0; j < 4; j++)
                    a[j] += cg * winA[24 + j - t];
            }
        }
        {
            float winB[12];
            #pragma unroll
            for (int kk = 0; kk < 3; kk++) {
                float4 qv = xs4[hq - 2 + kk];
                winB[4*kk+0] = qv.x; winB[4*kk+1] = qv.y;
                winB[4*kk+2] = qv.z; winB[4*kk+3] = qv.w;
            }
            #pragma unroll
            for (int t = 0; t < 9; t++) {
                float cg = cs[t].x;
                #pragma unroll
                for (int j = 0; j < 4; j++)
                    a[j] += cg * winB[8 + j - t];
            }
        }
        v1w[hq] = make_float4(a[0], a[1], a[2], a[3]);
    }
    __syncwarp();      // the ONLY inter-stage barrier (warp-private plane)

    // ── stage B: v1 → w2 (h @4), w3 (ch2 @4), v3 (cg2 @4)
    {
        float w2[4] = {0,0,0,0}, w3[4] = {0,0,0,0}, v3[4] = {0,0,0,0};
        #pragma unroll
        for (int t = 0; t < 22; t++) {
            float4 qv = v1r[b4 - t];
            float2 c  = cs[t];
            v3[0] += c.x * qv.x; v3[1] += c.x * qv.y;
            v3[2] += c.x * qv.z; v3[3] += c.x * qv.w;
            w3[0] += c.y * qv.x; w3[1] += c.y * qv.y;
            w3[2] += c.y * qv.z; w3[3] += c.y * qv.w;
            if (t < 8) {
                w2[0] += h[t] * qv.x; w2[1] += h[t] * qv.y;
                w2[2] += h[t] * qv.z; w2[3] += h[t] * qv.w;
            }
        }

        float o[20];
        #pragma unroll
        for (int j = 0; j < 4; j++) {
            o[j*5 + 0] = w0[j];
            o[j*5 + 1] = w1[j];
            o[j*5 + 2] = w2[j];
            o[j*5 + 3] = w3[j];
            o[j*5 + 4] = v3[j];
        }
        const int bd = b * WL_D + dg * WL_G + p;
        const int m0 = M0 + 4 * lane;
        float4* og = (float4*)(out + ((size_t)bd * WL_L + m0) * 5);
        #pragma unroll
        for (int kk = 0; kk < 5; kk++) og[kk] = ((const float4*)o)[kk];
    }
}

extern "C" void kernel_launch(void* const* d_in, const int* in_sizes, int n_in,
                              void* d_out, int out_size) {
    const float* x     = (const float*)d_in[0];
    const float* w_dec = (const float*)d_in[1];
    const float* v_dec = (const float*)d_in[2];
    float* out = (float*)d_out;

    wavelet_db4_kernel<<<WL_B * WL_NDG * WL_NCHUNK, WL_NT>>>(x, w_dec, v_dec, out);
}

// round 11
// speedup vs baseline: 1.1215x; 1.1215x over previous
#include <cuda_runtime.h>

#define WL_L      2048
#define WL_LMASK  2047
#define WL_D      32
#define WL_B      16
#define WL_NT     256                 // 8 warps, one per d-plane

#define WL_G      8                   // d-planes per CTA
#define WL_T      128                 // outputs per plane per CTA
#define WL_HALO   112                 // >= 105 back-reach, multiple of 4
#define WL_EXT    (WL_T + WL_HALO)    // 240 floats = 60 quads
#define WL_NCHUNK (WL_L / WL_T)       // 16
#define WL_NDG    (WL_D / WL_G)       // 4

__global__ __launch_bounds__(WL_NT) void wavelet_db4_kernel(
    const float* __restrict__ x,       // (B, L, D)
    const float* __restrict__ w_dec,   // (4, L, L) — only 8 taps read
    const float* __restrict__ v_dec,   // (4, L, L) — only 8 taps read
    float* __restrict__ out)           // (B, D, L, 5)
{
    __shared__ __align__(16) float xs [WL_G][WL_EXT];
    __shared__ __align__(16) float v0s[WL_G][WL_EXT];
    __shared__ __align__(16) float v1s[WL_G][WL_EXT];
    __shared__ __align__(16) float v2s[WL_G][WL_EXT];
    __shared__ float gs[8];
    __shared__ float hs[8];

    const int tid   = threadIdx.x;
    const int blk   = blockIdx.x;
    const int chunk = blk & (WL_NCHUNK - 1);
    const int dg    = (blk >> 4) & (WL_NDG - 1);
    const int b     = blk >> 6;
    const int M0    = chunk * WL_T;
    const int base  = M0 - WL_HALO;

    const int p    = tid >> 5;        // plane 0..7 == warp id
    const int lane = tid & 31;
    const int hq   = lane - 4;        // halo quad id 0..27 on lanes 4..31

    // taps from row 0 of level-0 filters: f[0][0][(0-i) mod L] = tap[i]
    if (tid < 8) {
        int col = (WL_L - tid) & WL_LMASK;
        gs[tid] = v_dec[col];
        hs[tid] = w_dec[col];
    }

    // gather: 8 adjacent d per x-row (two LDG.128), one row per thread
    if (tid < WL_EXT) {
        const float* xp = x + ((size_t)b * WL_L * WL_D) + dg * WL_G;
        int gl = (base + tid) & WL_LMASK;
        const float4* rp = (const float4*)(xp + (size_t)gl * WL_D);
        float4 q0 = rp[0], q1 = rp[1];
        xs[0][tid] = q0.x; xs[1][tid] = q0.y; xs[2][tid] = q0.z; xs[3][tid] = q0.w;
        xs[4][tid] = q1.x; xs[5][tid] = q1.y; xs[6][tid] = q1.z; xs[7][tid] = q1.w;
    }
    __syncthreads();   // the ONLY CTA-wide barrier

    float g[8], h[8];
    #pragma unroll
    for (int i = 0; i < 8; i++) { g[i] = gs[i]; h[i] = hs[i]; }

    const float4* xs4  = (const float4*)(&xs [p][0]);
    const float4* v0s4 = (const float4*)(&v0s[p][0]);
    const float4* v1s4 = (const float4*)(&v1s[p][0]);
    const float4* v2s4 = (const float4*)(&v2s[p][0]);
    float4* v0s4w = (float4*)(&v0s[p][0]);
    float4* v1s4w = (float4*)(&v1s[p][0]);
    float4* v2s4w = (float4*)(&v2s[p][0]);

    const int b4 = 28 + lane;         // this thread's output quad (28..59)

    float w0[4], w1[4], w2[4];

    // ── stage 1: dilation 1 on xs → v0 (g) + w0 (h), window loaded once
    {
        int wb = b4 - 2;
        float4 A = xs4[wb], B = xs4[wb + 1], C = xs4[wb + 2];
        float win[12] = {A.x,A.y,A.z,A.w, B.x,B.y,B.z,B.w, C.x,C.y,C.z,C.w};
        float vg[4] = {0,0,0,0};
        #pragma unroll
        for (int j = 0; j < 4; j++) w0[j] = 0.f;
        #pragma unroll
        for (int i = 0; i < 8; i++) {
            #pragma unroll
            for (int j = 0; j < 4; j++) {
                vg[j] += g[i] * win[8 + j - i];
                w0[j] += h[i] * win[8 + j - i];
            }
        }
        v0s4w[b4] = make_float4(vg[0], vg[1], vg[2], vg[3]);

        if (hq >= 2) {                // halo v0 (g only), l0h >= 8
            int wbh = hq - 2;
            float4 HA = xs4[wbh], HB = xs4[wbh + 1], HC = xs4[wbh + 2];
            float hw[12] = {HA.x,HA.y,HA.z,HA.w, HB.x,HB.y,HB.z,HB.w, HC.x,HC.y,HC.z,HC.w};
            float a0=0.f, a1=0.f, a2=0.f, a3=0.f;
            #pragma unroll
            for (int i = 0; i < 8; i++) {
                a0 += g[i] * hw[ 8 - i]; a1 += g[i] * hw[ 9 - i];
                a2 += g[i] * hw[10 - i]; a3 += g[i] * hw[11 - i];
            }
            v0s4w[hq] = make_float4(a0, a1, a2, a3);
        }
    }
    __syncwarp();

    // ── stage 2: dilation 2 on v0 → v1 (g) + w1 (h)
    {
        int wb = b4 - 4;
        float win[20];
        #pragma unroll
        for (int kk = 0; kk < 5; kk++) {
            float4 qv = v0s4[wb + kk];
            win[4*kk] = qv.x; win[4*kk+1] = qv.y; win[4*kk+2] = qv.z; win[4*kk+3] = qv.w;
        }
        float vg[4] = {0,0,0,0};
        #pragma unroll
        for (int j = 0; j < 4; j++) w1[j] = 0.f;
        #pragma unroll
        for (int i = 0; i < 8; i++) {
            #pragma unroll
            for (int j = 0; j < 4; j++) {
                vg[j] += g[i] * win[16 + j - 2*i];
                w1[j] += h[i] * win[16 + j - 2*i];
            }
        }
        v1s4w[b4] = make_float4(vg[0], vg[1], vg[2], vg[3]);

        if (hq >= 7) {                // halo v1 (g only), l0h >= 28
            int wbh = hq - 4;
            float hw[20];
            #pragma unroll
            for (int kk = 0; kk < 5; kk++) {
                float4 qv = v0s4[wbh + kk];
                hw[4*kk] = qv.x; hw[4*kk+1] = qv.y; hw[4*kk+2] = qv.z; hw[4*kk+3] = qv.w;
            }
            float a0=0.f, a1=0.f, a2=0.f, a3=0.f;
            #pragma unroll
            for (int i = 0; i < 8; i++) {
                a0 += g[i] * hw[16 - 2*i]; a1 += g[i] * hw[17 - 2*i];
                a2 += g[i] * hw[18 - 2*i]; a3 += g[i] * hw[19 - 2*i];
            }
            v1s4w[hq] = make_float4(a0, a1, a2, a3);
        }
    }
    __syncwarp();

    // ── stage 3: dilation 4 on v1 → v2 (g) + w2 (h); one float4 per tap
    {
        float vg[4] = {0,0,0,0};
        #pragma unroll
        for (int j = 0; j < 4; j++) w2[j] = 0.f;
        #pragma unroll
        for (int i = 0; i < 8; i++) {
            float4 qv = v1s4[b4 - i];
            vg[0] += g[i] * qv.x; vg[1] += g[i] * qv.y;
            vg[2] += g[i] * qv.z; vg[3] += g[i] * qv.w;
            w2[0] += h[i] * qv.x; w2[1] += h[i] * qv.y;
            w2[2] += h[i] * qv.z; w2[3] += h[i] * qv.w;
        }
        v2s4w[b4] = make_float4(vg[0], vg[1], vg[2], vg[3]);

        if (hq >= 14) {               // halo v2 (g only), l0h >= 56
            float a0=0.f, a1=0.f, a2=0.f, a3=0.f;
            #pragma unroll
            for (int i = 0; i < 8; i++) {
                float4 qv = v1s4[hq - i];
                a0 += g[i] * qv.x; a1 += g[i] * qv.y;
                a2 += g[i] * qv.z; a3 += g[i] * qv.w;
            }
            v2s4w[hq] = make_float4(a0, a1, a2, a3);
        }
    }
    __syncwarp();

    // ── stage 4: dilation 8 on v2 → w3 (h) + v3 (g); write all 5 coeffs
    {
        float w3[4] = {0,0,0,0}, v3[4] = {0,0,0,0};
        #pragma unroll
        for (int i = 0; i < 8; i++) {
            float4 qv = v2s4[b4 - 2*i];
            w3[0] += h[i] * qv.x; w3[1] += h[i] * qv.y;
            w3[2] += h[i] * qv.z; w3[3] += h[i] * qv.w;
            v3[0] += g[i] * qv.x; v3[1] += g[i] * qv.y;
            v3[2] += g[i] * qv.z; v3[3] += g[i] * qv.w;
        }

        float o[20];
        #pragma unroll
        for (int j = 0; j < 4; j++) {
            o[j*5 + 0] = w0[j];
            o[j*5 + 1] = w1[j];
            o[j*5 + 2] = w2[j];
            o[j*5 + 3] = w3[j];
            o[j*5 + 4] = v3[j];
        }
        const int bd = b * WL_D + dg * WL_G + p;
        const int m0 = M0 + 4 * lane;
        float4* og = (float4*)(out + ((size_t)bd * WL_L + m0) * 5);
        #pragma unroll
        for (int kk = 0; kk < 5; kk++) og[kk] = ((const float4*)o)[kk];
    }
}

extern "C" void kernel_launch(void* const* d_in, const int* in_sizes, int n_in,
                              void* d_out, int out_size) {
    const float* x     = (const float*)d_in[0];
    const float* w_dec = (const float*)d_in[1];
    const float* v_dec = (const float*)d_in[2];
    float* out = (float*)d_out;

    wavelet_db4_kernel<<<WL_B * WL_NDG * WL_NCHUNK, WL_NT>>>(x, w_dec, v_dec, out);
}

// round 12
// speedup vs baseline: 1.1650x; 1.0388x over previous
#include <cuda_runtime.h>

#define WL_L      2048
#define WL_LMASK  2047
#define WL_D      32
#define WL_B      16
#define WL_NT     256                 // 8 warps; 2 warps per d-plane

#define WL_G      4                   // d-planes per CTA
#define WL_T      256                 // outputs per plane per CTA
#define WL_HALO   112                 // >= 105 back-reach, multiple of 4
#define WL_EXT    (WL_T + WL_HALO)    // 368 floats = 92 quads
#define WL_NCHUNK (WL_L / WL_T)       // 8
#define WL_NDG    (WL_D / WL_G)       // 8

#define PLANE_BAR(pl) asm volatile("bar.sync %0, 64;" :: "r"((pl) + 1) : "memory")

__global__ __launch_bounds__(WL_NT) void wavelet_db4_kernel(
    const float* __restrict__ x,       // (B, L, D)
    const float* __restrict__ w_dec,   // (4, L, L) — only 8 taps read
    const float* __restrict__ v_dec,   // (4, L, L) — only 8 taps read
    float* __restrict__ out)           // (B, D, L, 5)
{
    __shared__ __align__(16) float xs [WL_G][WL_EXT];
    __shared__ __align__(16) float v0s[WL_G][WL_EXT];
    __shared__ __align__(16) float v1s[WL_G][WL_EXT];
    __shared__ __align__(16) float v2s[WL_G][WL_EXT];
    __shared__ float4 ws[WL_G][3][WL_T / 4];   // staged w0,w1,w2 quads
    __shared__ float gs[8];
    __shared__ float hs[8];

    const int tid   = threadIdx.x;
    const int blk   = blockIdx.x;
    const int chunk = blk & (WL_NCHUNK - 1);
    const int dg    = (blk >> 3) & (WL_NDG - 1);
    const int b     = blk >> 6;
    const int M0    = chunk * WL_T;
    const int base  = M0 - WL_HALO;

    const int p  = tid >> 6;          // plane 0..3 (64 threads = 2 warps each)
    const int pq = tid & 63;          // slot in plane 0..63
    const int b4 = 28 + pq;           // this thread's output quad (28..91)
    const int hq = pq - 36;           // halo quad 2..27 on pq 38..63

    // taps from row 0 of level-0 filters: f[0][0][(0-i) mod L] = tap[i]
    if (tid < 8) {
        int col = (WL_L - tid) & WL_LMASK;
        gs[tid] = v_dec[col];
        hs[tid] = w_dec[col];
    }

    // amortized gather: one float4 across 4 adjacent d per x-row
    {
        const float* xp = x + ((size_t)b * WL_L * WL_D) + dg * WL_G;
        #pragma unroll
        for (int l = tid; l < WL_EXT; l += WL_NT) {
            int gl = (base + l) & WL_LMASK;
            float4 qv = *(const float4*)(xp + (size_t)gl * WL_D);
            xs[0][l] = qv.x; xs[1][l] = qv.y; xs[2][l] = qv.z; xs[3][l] = qv.w;
        }
    }
    __syncthreads();   // the ONLY CTA-wide barrier

    float g[8], h[8];
    #pragma unroll
    for (int i = 0; i < 8; i++) { g[i] = gs[i]; h[i] = hs[i]; }

    const float4* xs4  = (const float4*)(&xs [p][0]);
    const float4* v0s4 = (const float4*)(&v0s[p][0]);
    const float4* v1s4 = (const float4*)(&v1s[p][0]);
    const float4* v2s4 = (const float4*)(&v2s[p][0]);
    float4* v0s4w = (float4*)(&v0s[p][0]);
    float4* v1s4w = (float4*)(&v1s[p][0]);
    float4* v2s4w = (float4*)(&v2s[p][0]);

    // ── stage 1: dilation 1 on xs → v0 (g) + w0 (h→ws[0])
    {
        int wb = b4 - 2;
        float4 A = xs4[wb], B = xs4[wb + 1], C = xs4[wb + 2];
        float win[12] = {A.x,A.y,A.z,A.w, B.x,B.y,B.z,B.w, C.x,C.y,C.z,C.w};
        float vg[4] = {0,0,0,0}, vh[4] = {0,0,0,0};
        #pragma unroll
        for (int i = 0; i < 8; i++) {
            #pragma unroll
            for (int j = 0; j < 4; j++) {
                vg[j] += g[i] * win[8 + j - i];
                vh[j] += h[i] * win[8 + j - i];
            }
        }
        v0s4w[b4]    = make_float4(vg[0], vg[1], vg[2], vg[3]);
        ws[p][0][pq] = make_float4(vh[0], vh[1], vh[2], vh[3]);

        if (hq >= 2) {                // halo v0 (g only), quads 2..27
            int wbh = hq - 2;
            float4 HA = xs4[wbh], HB = xs4[wbh + 1], HC = xs4[wbh + 2];
            float hw[12] = {HA.x,HA.y,HA.z,HA.w, HB.x,HB.y,HB.z,HB.w, HC.x,HC.y,HC.z,HC.w};
            float a0=0.f, a1=0.f, a2=0.f, a3=0.f;
            #pragma unroll
            for (int i = 0; i < 8; i++) {
                a0 += g[i] * hw[ 8 - i]; a1 += g[i] * hw[ 9 - i];
                a2 += g[i] * hw[10 - i]; a3 += g[i] * hw[11 - i];
            }
            v0s4w[hq] = make_float4(a0, a1, a2, a3);
        }
    }
    PLANE_BAR(p);

    // ── stage 2: dilation 2 on v0 → v1 (g) + w1 (h→ws[1])
    {
        int wb = b4 - 4;
        float win[20];
        #pragma unroll
        for (int kk = 0; kk < 5; kk++) {
            float4 qv = v0s4[wb + kk];
            win[4*kk] = qv.x; win[4*kk+1] = qv.y; win[4*kk+2] = qv.z; win[4*kk+3] = qv.w;
        }
        float vg[4] = {0,0,0,0}, vh[4] = {0,0,0,0};
        #pragma unroll
        for (int i = 0; i < 8; i++) {
            #pragma unroll
            for (int j = 0; j < 4; j++) {
                vg[j] += g[i] * win[16 + j - 2*i];
                vh[j] += h[i] * win[16 + j - 2*i];
            }
        }
        v1s4w[b4]    = make_float4(vg[0], vg[1], vg[2], vg[3]);
        ws[p][1][pq] = make_float4(vh[0], vh[1], vh[2], vh[3]);

        if (hq >= 7) {                // halo v1 (g only), quads 7..27
            int wbh = hq - 4;
            float hw[20];
            #pragma unroll
            for (int kk = 0; kk < 5; kk++) {
                float4 qv = v0s4[wbh + kk];
                hw[4*kk] = qv.x; hw[4*kk+1] = qv.y; hw[4*kk+2] = qv.z; hw[4*kk+3] = qv.w;
            }
            float a0=0.f, a1=0.f, a2=0.f, a3=0.f;
            #pragma unroll
            for (int i = 0; i < 8; i++) {
                a0 += g[i] * hw[16 - 2*i]; a1 += g[i] * hw[17 - 2*i];
                a2 += g[i] * hw[18 - 2*i]; a3 += g[i] * hw[19 - 2*i];
            }
            v1s4w[hq] = make_float4(a0, a1, a2, a3);
        }
    }
    PLANE_BAR(p);

    // ── stage 3: dilation 4 on v1 → v2 (g) + w2 (h→ws[2]); one float4 per tap
    {
        float vg[4] = {0,0,0,0}, vh[4] = {0,0,0,0};
        #pragma unroll
        for (int i = 0; i < 8; i++) {
            float4 qv = v1s4[b4 - i];
            vg[0] += g[i] * qv.x; vg[1] += g[i] * qv.y;
            vg[2] += g[i] * qv.z; vg[3] += g[i] * qv.w;
            vh[0] += h[i] * qv.x; vh[1] += h[i] * qv.y;
            vh[2] += h[i] * qv.z; vh[3] += h[i] * qv.w;
        }
        v2s4w[b4]    = make_float4(vg[0], vg[1], vg[2], vg[3]);
        ws[p][2][pq] = make_float4(vh[0], vh[1], vh[2], vh[3]);

        if (hq >= 14) {               // halo v2 (g only), quads 14..27
            float a0=0.f, a1=0.f, a2=0.f, a3=0.f;
            #pragma unroll
            for (int i = 0; i < 8; i++) {
                float4 qv = v1s4[hq - i];
                a0 += g[i] * qv.x; a1 += g[i] * qv.y;
                a2 += g[i] * qv.z; a3 += g[i] * qv.w;
            }
            v2s4w[hq] = make_float4(a0, a1, a2, a3);
        }
    }
    PLANE_BAR(p);

    // ── stage 4: dilation 8 on v2 → w3 (h) + v3 (g); pack with staged w0..w2
    {
        float w3[4] = {0,0,0,0}, v3[4] = {0,0,0,0};
        #pragma unroll
        for (int i = 0; i < 8; i++) {
            float4 qv = v2s4[b4 - 2*i];
            w3[0] += h[i] * qv.x; w3[1] += h[i] * qv.y;
            w3[2] += h[i] * qv.z; w3[3] += h[i] * qv.w;
            v3[0] += g[i] * qv.x; v3[1] += g[i] * qv.y;
            v3[2] += g[i] * qv.z; v3[3] += g[i] * qv.w;
        }

        float4 w0q = ws[p][0][pq];
        float4 w1q = ws[p][1][pq];
        float4 w2q = ws[p][2][pq];
        float w0[4] = {w0q.x, w0q.y, w0q.z, w0q.w};
        float w1[4] = {w1q.x, w1q.y, w1q.z, w1q.w};
        float w2[4] = {w2q.x, w2q.y, w2q.z, w2q.w};

        float o[20];
        #pragma unroll
        for (int j = 0; j < 4; j++) {
            o[j*5 + 0] = w0[j];
            o[j*5 + 1] = w1[j];
            o[j*5 + 2] = w2[j];
            o[j*5 + 3] = w3[j];
            o[j*5 + 4] = v3[j];
        }
        const int bd = b * WL_D + dg * WL_G + p;
        const int m0 = M0 + 4 * pq;
        float4* og = (float4*)(out + ((size_t)bd * WL_L + m0) * 5);
        #pragma unroll
        for (int kk = 0; kk < 5; kk++) og[kk] = ((const float4*)o)[kk];
    }
}

extern "C" void kernel_launch(void* const* d_in, const int* in_sizes, int n_in,
                              void* d_out, int out_size) {
    const float* x     = (const float*)d_in[0];
    const float* w_dec = (const float*)d_in[1];
    const float* v_dec = (const float*)d_in[2];
    float* out = (float*)d_out;

    wavelet_db4_kernel<<<WL_B * WL_NDG * WL_NCHUNK, WL_NT>>>(x, w_dec, v_dec, out);
}